// round 7
// baseline (speedup 1.0000x reference)
#include <cuda_runtime.h>
#include <cstdint>

#define NTOK 16384

// Scratch (allocation-free rule: __device__ globals)
__device__ float g_xp[33554432];   // x @ W_in
__device__ float g_y[33554432];    // attention output
__device__ float g_wt1[65536];     // W_in^T  [n][k], tf32-rounded fp32
__device__ float g_wt2[65536];     // W_out^T [n][k], tf32-rounded fp32

// ---------------------------------------------------------------------------
__device__ __forceinline__ uint32_t smem_u32(const void* p) {
    uint32_t a;
    asm("{ .reg .u64 t; cvta.to.shared.u64 t, %1; cvt.u32.u64 %0, t; }"
        : "=r"(a) : "l"(p));
    return a;
}
__device__ __forceinline__ float tf32r(float x) {
    uint32_t r;
    asm("cvt.rna.tf32.f32 %0, %1;" : "=r"(r) : "f"(x));
    return __uint_as_float(r);
}
__device__ __forceinline__ void mma_tf32(float* d, const uint32_t* a,
                                         const uint32_t* b) {
    asm volatile(
        "mma.sync.aligned.m16n8k8.row.col.f32.tf32.tf32.f32 "
        "{%0,%1,%2,%3}, {%4,%5,%6,%7}, {%8,%9}, {%0,%1,%2,%3};"
        : "+f"(d[0]), "+f"(d[1]), "+f"(d[2]), "+f"(d[3])
        : "r"(a[0]), "r"(a[1]), "r"(a[2]), "r"(a[3]), "r"(b[0]), "r"(b[1]));
}
#define CP_ASYNC16(dst, src) \
    asm volatile("cp.async.ca.shared.global [%0], [%1], 16;" \
                 :: "r"(dst), "l"(src))
#define CP_COMMIT() asm volatile("cp.async.commit_group;")
#define CP_WAIT0()  asm volatile("cp.async.wait_group 0;")

// ---------------------------------------------------------------------------
// Transpose + tf32 RN-round: Wt[n][k] = round_tf32(W[k][n]), 256x256
// ---------------------------------------------------------------------------
__global__ void transpose_tf32(const float* __restrict__ W, float* __restrict__ Wt)
{
    __shared__ float tile[32][33];
    const int bx = (blockIdx.x & 7) << 5;
    const int by = (blockIdx.x >> 3) << 5;
    const int tx = threadIdx.x & 31;
    const int ty = threadIdx.x >> 5;
#pragma unroll
    for (int i = 0; i < 32; i += 8)
        tile[ty + i][tx] = W[(by + ty + i) * 256 + bx + tx];
    __syncthreads();
#pragma unroll
    for (int i = 0; i < 32; i += 8)
        Wt[(bx + ty + i) * 256 + by + tx] = tf32r(tile[tx][ty + i]);
}

// ---------------------------------------------------------------------------
// Single-pass TF32 GEMM: C[M x 256] = A @ Bt^T + bias  (unchanged from R5)
// ---------------------------------------------------------------------------
#define AST 36
#define ABUF_B (128 * AST * 4)            // 18432
#define BUFB   (2 * ABUF_B)               // 36864 (A + B)
#define GEMM_SMEM (2 * BUFB)              // 73728

__global__ __launch_bounds__(256) void gemm_tf32(const float* __restrict__ A,
                                                 const float* __restrict__ Bt,
                                                 const float* __restrict__ bias,
                                                 float* __restrict__ C)
{
    extern __shared__ char sm[];
    const uint32_t smb = smem_u32(sm);
    const int t    = threadIdx.x;
    const int lane = t & 31;
    const int warp = t >> 5;
    const int wm0  = (warp >> 2) * 64;
    const int wn0  = (warp & 3) * 32;
    const int row0 = blockIdx.y << 7;
    const int col0 = blockIdx.x << 7;
    const int g    = lane >> 2;
    const int tg   = lane & 3;

    const int lr = t >> 3;          // 0..31
    const int lk = (t & 7) << 2;    // 0,4,...,28

    float acc[4][4][4];
#pragma unroll
    for (int i = 0; i < 4; i++)
#pragma unroll
        for (int j = 0; j < 4; j++)
#pragma unroll
            for (int k = 0; k < 4; k++) acc[i][j][k] = 0.f;

    float4 pa[4];

#define B_ASYNC(k0, bufoff)                                                    \
    do {                                                                       \
        _Pragma("unroll")                                                      \
        for (int i = 0; i < 4; i++) {                                          \
            const int n = i * 32 + lr;                                         \
            CP_ASYNC16(smb + (bufoff) + ABUF_B + (uint32_t)(n * AST + lk) * 4, \
                       Bt + (size_t)(col0 + n) * 256 + (k0) + lk);             \
        }                                                                      \
        CP_COMMIT();                                                           \
    } while (0)

#define A_LOAD(k0)                                                             \
    do {                                                                       \
        _Pragma("unroll")                                                      \
        for (int i = 0; i < 4; i++)                                            \
            pa[i] = *(const float4*)(A + (size_t)(row0 + i * 32 + lr) * 256 +  \
                                     (k0) + lk);                               \
    } while (0)

#define A_STORE(bufoff)                                                        \
    do {                                                                       \
        _Pragma("unroll")                                                      \
        for (int i = 0; i < 4; i++) {                                          \
            float4 v;                                                          \
            v.x = tf32r(pa[i].x); v.y = tf32r(pa[i].y);                        \
            v.z = tf32r(pa[i].z); v.w = tf32r(pa[i].w);                        \
            *(float4*)(sm + (bufoff) + (uint32_t)((i * 32 + lr) * AST + lk) * 4) = v; \
        }                                                                      \
    } while (0)

    A_LOAD(0);
    B_ASYNC(0, 0);
    A_STORE(0);
    CP_WAIT0();
    __syncthreads();

    for (int c = 0; c < 8; c++) {
        const uint32_t cur = (uint32_t)(c & 1) * BUFB;
        const uint32_t nxt = BUFB - cur;
        if (c < 7) {
            B_ASYNC((c + 1) * 32, nxt);
            A_LOAD((c + 1) * 32);
        }

        const float* As = (const float*)(sm + cur);
        const float* Bs = (const float*)(sm + cur + ABUF_B);

#pragma unroll
        for (int ks = 0; ks < 4; ks++) {
            const int kk = ks * 8;
            uint32_t af[4][4], bf[4][2];
#pragma unroll
            for (int mf = 0; mf < 4; mf++) {
                const int r = wm0 + mf * 16 + g;
                af[mf][0] = __float_as_uint(As[r * AST + kk + tg]);
                af[mf][1] = __float_as_uint(As[(r + 8) * AST + kk + tg]);
                af[mf][2] = __float_as_uint(As[r * AST + kk + tg + 4]);
                af[mf][3] = __float_as_uint(As[(r + 8) * AST + kk + tg + 4]);
            }
#pragma unroll
            for (int nf = 0; nf < 4; nf++) {
                const int n = wn0 + nf * 8 + g;
                bf[nf][0] = __float_as_uint(Bs[n * AST + kk + tg]);
                bf[nf][1] = __float_as_uint(Bs[n * AST + kk + tg + 4]);
            }
#pragma unroll
            for (int mf = 0; mf < 4; mf++)
#pragma unroll
                for (int nf = 0; nf < 4; nf++)
                    mma_tf32(acc[mf][nf], af[mf], bf[nf]);
        }

        if (c < 7) {
            A_STORE(nxt);
            CP_WAIT0();
        }
        __syncthreads();
    }

#pragma unroll
    for (int nf = 0; nf < 4; nf++) {
        const int cc = col0 + wn0 + nf * 8 + tg * 2;
        const float b0 = bias[cc], b1 = bias[cc + 1];
#pragma unroll
        for (int mf = 0; mf < 4; mf++) {
            const int r = row0 + wm0 + mf * 16 + g;
            float2 o0 = make_float2(acc[mf][nf][0] + b0, acc[mf][nf][1] + b1);
            float2 o1 = make_float2(acc[mf][nf][2] + b0, acc[mf][nf][3] + b1);
            *(float2*)(C + (size_t)r * 256 + cc) = o0;
            *(float2*)(C + (size_t)(r + 8) * 256 + cc) = o1;
        }
    }
}

// ---------------------------------------------------------------------------
// TF32-MMA attention: per (h,b,blk): D(64x32) = A(64x80) @ X(80x32).
//   A staged [q][k] stride 84 (a-frag LDS conflict-free: bank=20g+tg+C).
//   X staged TRANSPOSED [ch][tok] stride 84 (b-frag conflict-free, same math).
//   4 warps split M (16 rows each); 40 MMA/warp; 128 thr/CTA; grid 16384.
// ---------------------------------------------------------------------------
__global__ __launch_bounds__(128) void attn_mma(const float* __restrict__ aw,
                                                const int*   __restrict__ idx,
                                                const float* __restrict__ wsel)
{
    __shared__ float sA[64 * 84];    // A[q][k], 80+4 pad
    __shared__ float sXT[32 * 84];   // X^T[ch][tok], 80+4 pad

    const int t    = threadIdx.x;
    const int bid  = blockIdx.x;
    const int blk  = bid & 255;
    const int b    = (bid >> 8) & 7;
    const int h    = bid >> 11;
    const int bh   = blk >> 4;
    const int bw   = blk & 15;
    const int lane = t & 31;
    const int warp = t >> 5;
    const int g    = lane >> 2;
    const int tg   = lane & 3;

    // ---- stage A (64x80 contiguous): 1280 float4, 10/thread, tf32-rounded
    const float* Ab = aw + (size_t)bid * 5120;
#pragma unroll
    for (int i = 0; i < 10; i++) {
        const int v = i * 128 + t;
        const int q = v / 20;
        const int m = v % 20;
        const float4 a = *(const float4*)(Ab + q * 80 + m * 4);
        float* d = sA + q * 84 + m * 4;
        d[0] = tf32r(a.x); d[1] = tf32r(a.y);
        d[2] = tf32r(a.z); d[3] = tf32r(a.w);
    }

    const size_t xbase = (size_t)b * NTOK * 256 + h * 32;

    // ---- stage X^T: local 64 tokens (512 float4, 4/thread), transposed store
#pragma unroll
    for (int i = 0; i < 4; i++) {
        const int v  = i * 128 + t;
        const int p  = v >> 3;          // token 0..63
        const int dq = v & 7;           // channel quad
        const int r  = p >> 3, c = p & 7;
        const int sp = (bh * 8 + r) * 128 + bw * 8 + c;
        const float4 x = *(const float4*)(g_xp + xbase + (size_t)sp * 256 + dq * 4);
        sXT[(dq * 4 + 0) * 84 + p] = tf32r(x.x);
        sXT[(dq * 4 + 1) * 84 + p] = tf32r(x.y);
        sXT[(dq * 4 + 2) * 84 + p] = tf32r(x.z);
        sXT[(dq * 4 + 3) * 84 + p] = tf32r(x.w);
    }
    // ---- stage X^T: selected 16 tokens (128 float4, 1/thread), weighted
    {
        const int j    = t >> 3;
        const int dq   = t & 7;
        const int base = (b * 256 + blk) * 16 + j;
        const int tok  = idx[base];
        const float w  = wsel[base];
        const float4 x = *(const float4*)(g_xp + xbase + (size_t)tok * 256 + dq * 4);
        sXT[(dq * 4 + 0) * 84 + 64 + j] = tf32r(x.x * w);
        sXT[(dq * 4 + 1) * 84 + 64 + j] = tf32r(x.y * w);
        sXT[(dq * 4 + 2) * 84 + 64 + j] = tf32r(x.z * w);
        sXT[(dq * 4 + 3) * 84 + 64 + j] = tf32r(x.w * w);
    }
    __syncthreads();

    // ---- MMA: warp handles rows [m0, m0+16); 10 k-steps x 4 n-tiles
    const int m0 = warp << 4;
    float acc[4][4];
#pragma unroll
    for (int i = 0; i < 4; i++)
#pragma unroll
        for (int j = 0; j < 4; j++) acc[i][j] = 0.f;

#pragma unroll
    for (int ks = 0; ks < 10; ks++) {
        const int kk = ks * 8;
        uint32_t af[4];
        af[0] = __float_as_uint(sA[(m0 + g) * 84 + kk + tg]);
        af[1] = __float_as_uint(sA[(m0 + g + 8) * 84 + kk + tg]);
        af[2] = __float_as_uint(sA[(m0 + g) * 84 + kk + tg + 4]);
        af[3] = __float_as_uint(sA[(m0 + g + 8) * 84 + kk + tg + 4]);
#pragma unroll
        for (int nf = 0; nf < 4; nf++) {
            uint32_t bf[2];
            bf[0] = __float_as_uint(sXT[(nf * 8 + g) * 84 + kk + tg]);
            bf[1] = __float_as_uint(sXT[(nf * 8 + g) * 84 + kk + tg + 4]);
            mma_tf32(acc[nf], af, bf);
        }
    }

    // ---- scatter D to token-major y (c-frag: rows g/g+8, cols 2tg/2tg+1)
#pragma unroll
    for (int nf = 0; nf < 4; nf++) {
#pragma unroll
        for (int half = 0; half < 2; half++) {
            const int q  = m0 + g + half * 8;
            const int r  = q >> 3, c = q & 7;
            const int sp = (bh * 8 + r) * 128 + bw * 8 + c;
            const float2 o = make_float2(acc[nf][half * 2 + 0],
                                         acc[nf][half * 2 + 1]);
            *(float2*)(g_y + xbase + (size_t)sp * 256 + nf * 8 + tg * 2) = o;
        }
    }
}

// ===========================================================================
extern "C" void kernel_launch(void* const* d_in, const int* in_sizes, int n_in,
                              void* d_out, int out_size)
{
    const float* x    = (const float*)d_in[0];
    const float* aw   = (const float*)d_in[1];
    const int*   idx  = (const int*)d_in[2];
    const float* wsel = (const float*)d_in[3];
    const float* Win  = (const float*)d_in[4];
    const float* bin  = (const float*)d_in[5];
    const float* Wout = (const float*)d_in[6];
    const float* bout = (const float*)d_in[7];
    float* out = (float*)d_out;

    float *xp_ptr, *y_ptr, *wt1, *wt2;
    cudaGetSymbolAddress((void**)&xp_ptr, g_xp);
    cudaGetSymbolAddress((void**)&y_ptr, g_y);
    cudaGetSymbolAddress((void**)&wt1, g_wt1);
    cudaGetSymbolAddress((void**)&wt2, g_wt2);

    cudaFuncSetAttribute(gemm_tf32,
                         cudaFuncAttributeMaxDynamicSharedMemorySize, GEMM_SMEM);

    transpose_tf32<<<64, 256>>>(Win, wt1);
    transpose_tf32<<<64, 256>>>(Wout, wt2);

    gemm_tf32<<<dim3(2, 1024), 256, GEMM_SMEM>>>(x, wt1, bin, xp_ptr);
    attn_mma<<<16384, 128>>>(aw, idx, wsel);
    gemm_tf32<<<dim3(2, 1024), 256, GEMM_SMEM>>>(y_ptr, wt2, bout, out);
}

// round 8
// speedup vs baseline: 1.0299x; 1.0299x over previous
#include <cuda_runtime.h>
#include <cstdint>

#define NTOK 16384

// Scratch (allocation-free rule: __device__ globals)
__device__ float g_xp[33554432];   // x @ W_in
__device__ float g_y[33554432];    // attention output
__device__ float g_wt1[65536];     // W_in^T  [n][k], tf32-rounded fp32
__device__ float g_wt2[65536];     // W_out^T [n][k], tf32-rounded fp32

// ---------------------------------------------------------------------------
__device__ __forceinline__ uint32_t smem_u32(const void* p) {
    uint32_t a;
    asm("{ .reg .u64 t; cvta.to.shared.u64 t, %1; cvt.u32.u64 %0, t; }"
        : "=r"(a) : "l"(p));
    return a;
}
__device__ __forceinline__ float tf32r(float x) {
    uint32_t r;
    asm("cvt.rna.tf32.f32 %0, %1;" : "=r"(r) : "f"(x));
    return __uint_as_float(r);
}
__device__ __forceinline__ void mma_tf32(float* d, const uint32_t* a,
                                         const uint32_t* b) {
    asm volatile(
        "mma.sync.aligned.m16n8k8.row.col.f32.tf32.tf32.f32 "
        "{%0,%1,%2,%3}, {%4,%5,%6,%7}, {%8,%9}, {%0,%1,%2,%3};"
        : "+f"(d[0]), "+f"(d[1]), "+f"(d[2]), "+f"(d[3])
        : "r"(a[0]), "r"(a[1]), "r"(a[2]), "r"(a[3]), "r"(b[0]), "r"(b[1]));
}
#define CP_ASYNC16(dst, src) \
    asm volatile("cp.async.ca.shared.global [%0], [%1], 16;" \
                 :: "r"(dst), "l"(src))
#define CP_COMMIT() asm volatile("cp.async.commit_group;")
#define CP_WAIT0()  asm volatile("cp.async.wait_group 0;")

// ---------------------------------------------------------------------------
// Transpose + tf32 RN-round: Wt[n][k] = round_tf32(W[k][n]), 256x256
// ---------------------------------------------------------------------------
__global__ void transpose_tf32(const float* __restrict__ W, float* __restrict__ Wt)
{
    __shared__ float tile[32][33];
    const int bx = (blockIdx.x & 7) << 5;
    const int by = (blockIdx.x >> 3) << 5;
    const int tx = threadIdx.x & 31;
    const int ty = threadIdx.x >> 5;
#pragma unroll
    for (int i = 0; i < 32; i += 8)
        tile[ty + i][tx] = W[(by + ty + i) * 256 + bx + tx];
    __syncthreads();
#pragma unroll
    for (int i = 0; i < 32; i += 8)
        Wt[(bx + ty + i) * 256 + by + tx] = tf32r(tile[tx][ty + i]);
}

// ---------------------------------------------------------------------------
// Single-pass TF32 GEMM: C[M x 256] = A @ Bt^T + bias  (unchanged; at floor)
// ---------------------------------------------------------------------------
#define AST 36
#define ABUF_B (128 * AST * 4)            // 18432
#define BUFB   (2 * ABUF_B)               // 36864 (A + B)
#define GEMM_SMEM (2 * BUFB)              // 73728

__global__ __launch_bounds__(256) void gemm_tf32(const float* __restrict__ A,
                                                 const float* __restrict__ Bt,
                                                 const float* __restrict__ bias,
                                                 float* __restrict__ C)
{
    extern __shared__ char sm[];
    const uint32_t smb = smem_u32(sm);
    const int t    = threadIdx.x;
    const int lane = t & 31;
    const int warp = t >> 5;
    const int wm0  = (warp >> 2) * 64;
    const int wn0  = (warp & 3) * 32;
    const int row0 = blockIdx.y << 7;
    const int col0 = blockIdx.x << 7;
    const int g    = lane >> 2;
    const int tg   = lane & 3;

    const int lr = t >> 3;          // 0..31
    const int lk = (t & 7) << 2;    // 0,4,...,28

    float acc[4][4][4];
#pragma unroll
    for (int i = 0; i < 4; i++)
#pragma unroll
        for (int j = 0; j < 4; j++)
#pragma unroll
            for (int k = 0; k < 4; k++) acc[i][j][k] = 0.f;

    float4 pa[4];

#define B_ASYNC(k0, bufoff)                                                    \
    do {                                                                       \
        _Pragma("unroll")                                                      \
        for (int i = 0; i < 4; i++) {                                          \
            const int n = i * 32 + lr;                                         \
            CP_ASYNC16(smb + (bufoff) + ABUF_B + (uint32_t)(n * AST + lk) * 4, \
                       Bt + (size_t)(col0 + n) * 256 + (k0) + lk);             \
        }                                                                      \
        CP_COMMIT();                                                           \
    } while (0)

#define A_LOAD(k0)                                                             \
    do {                                                                       \
        _Pragma("unroll")                                                      \
        for (int i = 0; i < 4; i++)                                            \
            pa[i] = *(const float4*)(A + (size_t)(row0 + i * 32 + lr) * 256 +  \
                                     (k0) + lk);                               \
    } while (0)

#define A_STORE(bufoff)                                                        \
    do {                                                                       \
        _Pragma("unroll")                                                      \
        for (int i = 0; i < 4; i++) {                                          \
            float4 v;                                                          \
            v.x = tf32r(pa[i].x); v.y = tf32r(pa[i].y);                        \
            v.z = tf32r(pa[i].z); v.w = tf32r(pa[i].w);                        \
            *(float4*)(sm + (bufoff) + (uint32_t)((i * 32 + lr) * AST + lk) * 4) = v; \
        }                                                                      \
    } while (0)

    A_LOAD(0);
    B_ASYNC(0, 0);
    A_STORE(0);
    CP_WAIT0();
    __syncthreads();

    for (int c = 0; c < 8; c++) {
        const uint32_t cur = (uint32_t)(c & 1) * BUFB;
        const uint32_t nxt = BUFB - cur;
        if (c < 7) {
            B_ASYNC((c + 1) * 32, nxt);
            A_LOAD((c + 1) * 32);
        }

        const float* As = (const float*)(sm + cur);
        const float* Bs = (const float*)(sm + cur + ABUF_B);

#pragma unroll
        for (int ks = 0; ks < 4; ks++) {
            const int kk = ks * 8;
            uint32_t af[4][4], bf[4][2];
#pragma unroll
            for (int mf = 0; mf < 4; mf++) {
                const int r = wm0 + mf * 16 + g;
                af[mf][0] = __float_as_uint(As[r * AST + kk + tg]);
                af[mf][1] = __float_as_uint(As[(r + 8) * AST + kk + tg]);
                af[mf][2] = __float_as_uint(As[r * AST + kk + tg + 4]);
                af[mf][3] = __float_as_uint(As[(r + 8) * AST + kk + tg + 4]);
            }
#pragma unroll
            for (int nf = 0; nf < 4; nf++) {
                const int n = wn0 + nf * 8 + g;
                bf[nf][0] = __float_as_uint(Bs[n * AST + kk + tg]);
                bf[nf][1] = __float_as_uint(Bs[n * AST + kk + tg + 4]);
            }
#pragma unroll
            for (int mf = 0; mf < 4; mf++)
#pragma unroll
                for (int nf = 0; nf < 4; nf++)
                    mma_tf32(acc[mf][nf], af[mf], bf[nf]);
        }

        if (c < 7) {
            A_STORE(nxt);
            CP_WAIT0();
        }
        __syncthreads();
    }

#pragma unroll
    for (int nf = 0; nf < 4; nf++) {
        const int cc = col0 + wn0 + nf * 8 + tg * 2;
        const float b0 = bias[cc], b1 = bias[cc + 1];
#pragma unroll
        for (int mf = 0; mf < 4; mf++) {
            const int r = row0 + wm0 + mf * 16 + g;
            float2 o0 = make_float2(acc[mf][nf][0] + b0, acc[mf][nf][1] + b1);
            float2 o1 = make_float2(acc[mf][nf][2] + b0, acc[mf][nf][3] + b1);
            *(float2*)(C + (size_t)r * 256 + cc) = o0;
            *(float2*)(C + (size_t)(r + 8) * 256 + cc) = o1;
        }
    }
}

// ---------------------------------------------------------------------------
// TF32-MMA attention v2: per (h,b,blk): D(64x32) = A(64x80) @ X(80x32).
//   A-fragments are lane-unique -> load DIRECTLY from global (LDG + rna cvt),
//   no smem staging for A. X^T staged in smem (shared by all 4 warps).
//   smem ~10.8KB; __launch_bounds__(128,8) caps regs at 64 -> 8 CTAs/SM.
// ---------------------------------------------------------------------------
__global__ __launch_bounds__(128, 8) void attn_mma(const float* __restrict__ aw,
                                                   const int*   __restrict__ idx,
                                                   const float* __restrict__ wsel)
{
    __shared__ float sXT[32 * 84];   // X^T[ch][tok], 80+4 pad

    const int t    = threadIdx.x;
    const int bid  = blockIdx.x;
    const int blk  = bid & 255;
    const int b    = (bid >> 8) & 7;
    const int h    = bid >> 11;
    const int bh   = blk >> 4;
    const int bw   = blk & 15;
    const int lane = t & 31;
    const int warp = t >> 5;
    const int g    = lane >> 2;
    const int tg   = lane & 3;

    const size_t xbase = (size_t)b * NTOK * 256 + h * 32;

    // ---- stage X^T: local 64 tokens (512 float4, 4/thread), transposed store
#pragma unroll
    for (int i = 0; i < 4; i++) {
        const int v  = i * 128 + t;
        const int p  = v >> 3;          // token 0..63
        const int dq = v & 7;           // channel quad
        const int r  = p >> 3, c = p & 7;
        const int sp = (bh * 8 + r) * 128 + bw * 8 + c;
        const float4 x = *(const float4*)(g_xp + xbase + (size_t)sp * 256 + dq * 4);
        sXT[(dq * 4 + 0) * 84 + p] = tf32r(x.x);
        sXT[(dq * 4 + 1) * 84 + p] = tf32r(x.y);
        sXT[(dq * 4 + 2) * 84 + p] = tf32r(x.z);
        sXT[(dq * 4 + 3) * 84 + p] = tf32r(x.w);
    }
    // ---- stage X^T: selected 16 tokens (128 float4, 1/thread), weighted
    {
        const int j    = t >> 3;
        const int dq   = t & 7;
        const int base = (b * 256 + blk) * 16 + j;
        const int tok  = idx[base];
        const float w  = wsel[base];
        const float4 x = *(const float4*)(g_xp + xbase + (size_t)tok * 256 + dq * 4);
        sXT[(dq * 4 + 0) * 84 + 64 + j] = tf32r(x.x * w);
        sXT[(dq * 4 + 1) * 84 + 64 + j] = tf32r(x.y * w);
        sXT[(dq * 4 + 2) * 84 + 64 + j] = tf32r(x.z * w);
        sXT[(dq * 4 + 3) * 84 + 64 + j] = tf32r(x.w * w);
    }
    __syncthreads();

    // ---- MMA: warp handles rows [m0, m0+16); A-frags via direct LDG
    const int m0 = warp << 4;
    const float* Ar0 = aw + (size_t)bid * 5120 + (m0 + g) * 80;      // row q=m0+g
    const float* Ar1 = Ar0 + 8 * 80;                                  // row q+8

    float acc[4][4];
#pragma unroll
    for (int i = 0; i < 4; i++)
#pragma unroll
        for (int j = 0; j < 4; j++) acc[i][j] = 0.f;

#pragma unroll
    for (int ks = 0; ks < 10; ks++) {
        const int kk = ks * 8;
        uint32_t af[4];
        af[0] = __float_as_uint(tf32r(__ldg(Ar0 + kk + tg)));
        af[1] = __float_as_uint(tf32r(__ldg(Ar1 + kk + tg)));
        af[2] = __float_as_uint(tf32r(__ldg(Ar0 + kk + tg + 4)));
        af[3] = __float_as_uint(tf32r(__ldg(Ar1 + kk + tg + 4)));
#pragma unroll
        for (int nf = 0; nf < 4; nf++) {
            uint32_t bf[2];
            bf[0] = __float_as_uint(sXT[(nf * 8 + g) * 84 + kk + tg]);
            bf[1] = __float_as_uint(sXT[(nf * 8 + g) * 84 + kk + tg + 4]);
            mma_tf32(acc[nf], af, bf);
        }
    }

    // ---- scatter D to token-major y (c-frag: rows g/g+8, cols 2tg/2tg+1)
#pragma unroll
    for (int nf = 0; nf < 4; nf++) {
#pragma unroll
        for (int half = 0; half < 2; half++) {
            const int q  = m0 + g + half * 8;
            const int r  = q >> 3, c = q & 7;
            const int sp = (bh * 8 + r) * 128 + bw * 8 + c;
            const float2 o = make_float2(acc[nf][half * 2 + 0],
                                         acc[nf][half * 2 + 1]);
            *(float2*)(g_y + xbase + (size_t)sp * 256 + nf * 8 + tg * 2) = o;
        }
    }
}

// ===========================================================================
extern "C" void kernel_launch(void* const* d_in, const int* in_sizes, int n_in,
                              void* d_out, int out_size)
{
    const float* x    = (const float*)d_in[0];
    const float* aw   = (const float*)d_in[1];
    const int*   idx  = (const int*)d_in[2];
    const float* wsel = (const float*)d_in[3];
    const float* Win  = (const float*)d_in[4];
    const float* bin  = (const float*)d_in[5];
    const float* Wout = (const float*)d_in[6];
    const float* bout = (const float*)d_in[7];
    float* out = (float*)d_out;

    float *xp_ptr, *y_ptr, *wt1, *wt2;
    cudaGetSymbolAddress((void**)&xp_ptr, g_xp);
    cudaGetSymbolAddress((void**)&y_ptr, g_y);
    cudaGetSymbolAddress((void**)&wt1, g_wt1);
    cudaGetSymbolAddress((void**)&wt2, g_wt2);

    cudaFuncSetAttribute(gemm_tf32,
                         cudaFuncAttributeMaxDynamicSharedMemorySize, GEMM_SMEM);

    transpose_tf32<<<64, 256>>>(Win, wt1);
    transpose_tf32<<<64, 256>>>(Wout, wt2);

    gemm_tf32<<<dim3(2, 1024), 256, GEMM_SMEM>>>(x, wt1, bin, xp_ptr);
    attn_mma<<<16384, 128>>>(aw, idx, wsel);
    gemm_tf32<<<dim3(2, 1024), 256, GEMM_SMEM>>>(y_ptr, wt2, bout, out);
}

// round 9
// speedup vs baseline: 1.2657x; 1.2290x over previous
#include <cuda_runtime.h>
#include <cuda_fp16.h>
#include <cstdint>

#define NTOK 16384

// Scratch (allocation-free rule: __device__ globals)
__device__ float g_xp[33554432];   // x @ W_in
__device__ float g_y[33554432];    // attention output
__device__ __half g_wt1[65536];    // W_in^T  [n][k], fp16
__device__ __half g_wt2[65536];    // W_out^T [n][k], fp16

// ---------------------------------------------------------------------------
__device__ __forceinline__ uint32_t smem_u32(const void* p) {
    uint32_t a;
    asm("{ .reg .u64 t; cvta.to.shared.u64 t, %1; cvt.u32.u64 %0, t; }"
        : "=r"(a) : "l"(p));
    return a;
}
__device__ __forceinline__ float tf32r(float x) {
    uint32_t r;
    asm("cvt.rna.tf32.f32 %0, %1;" : "=r"(r) : "f"(x));
    return __uint_as_float(r);
}
__device__ __forceinline__ void mma_tf32(float* d, const uint32_t* a,
                                         const uint32_t* b) {
    asm volatile(
        "mma.sync.aligned.m16n8k8.row.col.f32.tf32.tf32.f32 "
        "{%0,%1,%2,%3}, {%4,%5,%6,%7}, {%8,%9}, {%0,%1,%2,%3};"
        : "+f"(d[0]), "+f"(d[1]), "+f"(d[2]), "+f"(d[3])
        : "r"(a[0]), "r"(a[1]), "r"(a[2]), "r"(a[3]), "r"(b[0]), "r"(b[1]));
}
__device__ __forceinline__ void mma_fp16(float* d, const uint32_t* a,
                                         const uint32_t* b) {
    asm volatile(
        "mma.sync.aligned.m16n8k16.row.col.f32.f16.f16.f32 "
        "{%0,%1,%2,%3}, {%4,%5,%6,%7}, {%8,%9}, {%0,%1,%2,%3};"
        : "+f"(d[0]), "+f"(d[1]), "+f"(d[2]), "+f"(d[3])
        : "r"(a[0]), "r"(a[1]), "r"(a[2]), "r"(a[3]), "r"(b[0]), "r"(b[1]));
}
#define LDSM4(R0, R1, R2, R3, addr) \
    asm volatile("ldmatrix.sync.aligned.m8n8.x4.shared.b16 {%0,%1,%2,%3}, [%4];" \
                 : "=r"(R0), "=r"(R1), "=r"(R2), "=r"(R3) : "r"(addr))

// ---------------------------------------------------------------------------
// Transpose + fp16 convert: Wt[n][k] = (half)W[k][n], 256x256
// ---------------------------------------------------------------------------
__global__ void transpose_half(const float* __restrict__ W,
                               __half* __restrict__ Wt)
{
    __shared__ float tile[32][33];
    const int bx = (blockIdx.x & 7) << 5;
    const int by = (blockIdx.x >> 3) << 5;
    const int tx = threadIdx.x & 31;
    const int ty = threadIdx.x >> 5;
#pragma unroll
    for (int i = 0; i < 32; i += 8)
        tile[ty + i][tx] = W[(by + ty + i) * 256 + bx + tx];
    __syncthreads();
#pragma unroll
    for (int i = 0; i < 32; i += 8)
        Wt[(bx + ty + i) * 256 + by + tx] = __float2half_rn(tile[tx][ty + i]);
}

// ---------------------------------------------------------------------------
// Single-pass FP16 warp-MMA GEMM: C[M x 256] = A @ Bt^T + bias
//   Bt fp16 [N][K] K-major. CTA 128x128, BK=32, 256 thr, 8 warps (2M x 4N),
//   warp tile 64x32, m16n8k16 frags via ldmatrix (R3-proven layout).
// ---------------------------------------------------------------------------
#define SROW 80                    // bytes per smem row (32 fp16 + 8 pad)
#define OFF_A 0
#define OFF_B 10240
#define BUFB  20480
#define GEMM_SMEM (2 * BUFB)       // 40960

__global__ __launch_bounds__(256) void gemm_fp16(const float* __restrict__ A,
                                                 const __half* __restrict__ Bt,
                                                 const float* __restrict__ bias,
                                                 float* __restrict__ C)
{
    extern __shared__ char sm[];
    const uint32_t smb = smem_u32(sm);
    const int t    = threadIdx.x;
    const int lane = t & 31;
    const int warp = t >> 5;
    const int wm0  = (warp >> 2) * 64;
    const int wn0  = (warp & 3) * 32;
    const int row0 = blockIdx.y << 7;
    const int col0 = blockIdx.x << 7;

    const int lr = t >> 3;          // 0..31
    const int lk = (t & 7) << 2;    // 0,4,...,28 (element offset)

    float acc[4][4][4];
#pragma unroll
    for (int i = 0; i < 4; i++)
#pragma unroll
        for (int j = 0; j < 4; j++)
#pragma unroll
            for (int k = 0; k < 4; k++) acc[i][j][k] = 0.f;

    float4 pa[4];
    uint2  pb[4];

    const uint32_t aoff = (uint32_t)(wm0 + (lane & 15)) * SROW + ((lane >> 4) << 4);
    const uint32_t boff = (uint32_t)(wn0 + (lane & 15)) * SROW + ((lane >> 4) << 4);

#define LOAD_CHUNK(k0)                                                          \
    do {                                                                        \
        _Pragma("unroll")                                                       \
        for (int i = 0; i < 4; i++) {                                           \
            const int r = i * 32 + lr;                                          \
            pa[i] = *(const float4*)(A  + (size_t)(row0 + r) * 256 + (k0) + lk); \
            pb[i] = *(const uint2*)(Bt + (size_t)(col0 + r) * 256 + (k0) + lk); \
        }                                                                       \
    } while (0)

#define STORE_CHUNK(bufoff)                                                     \
    do {                                                                        \
        char* base = sm + (bufoff);                                             \
        _Pragma("unroll")                                                       \
        for (int i = 0; i < 4; i++) {                                           \
            const int r = i * 32 + lr;                                          \
            const uint32_t off = (uint32_t)r * SROW + ((t & 7) << 3);           \
            uint2 h;                                                            \
            __half2 h0 = __floats2half2_rn(pa[i].x, pa[i].y);                   \
            __half2 h1 = __floats2half2_rn(pa[i].z, pa[i].w);                   \
            h.x = *(uint32_t*)&h0;                                              \
            h.y = *(uint32_t*)&h1;                                              \
            *(uint2*)(base + OFF_A + off) = h;                                  \
            *(uint2*)(base + OFF_B + off) = pb[i];                              \
        }                                                                       \
    } while (0)

    LOAD_CHUNK(0);
    STORE_CHUNK(0);
    __syncthreads();

    for (int c = 0; c < 8; c++) {
        const uint32_t cur = (uint32_t)(c & 1) * BUFB;
        const uint32_t nxt = BUFB - cur;
        if (c < 7) LOAD_CHUNK((c + 1) * 32);

        const uint32_t AB = smb + cur + OFF_A;
        const uint32_t BB = smb + cur + OFF_B;

#pragma unroll
        for (int ks = 0; ks < 2; ks++) {
            const uint32_t kb = ks * 32;   // bytes (16 halves)
            uint32_t ah[4][4], bf[4][2];
#pragma unroll
            for (int mf = 0; mf < 4; mf++)
                LDSM4(ah[mf][0], ah[mf][1], ah[mf][2], ah[mf][3],
                      AB + aoff + mf * (16 * SROW) + kb);
#pragma unroll
            for (int np = 0; np < 2; np++) {
                uint32_t r0, r1, r2, r3;
                LDSM4(r0, r1, r2, r3, BB + boff + np * (16 * SROW) + kb);
                bf[2 * np][0] = r0; bf[2 * np][1] = r2;
                bf[2 * np + 1][0] = r1; bf[2 * np + 1][1] = r3;
            }
#pragma unroll
            for (int mf = 0; mf < 4; mf++)
#pragma unroll
                for (int nf = 0; nf < 4; nf++)
                    mma_fp16(acc[mf][nf], ah[mf], bf[nf]);
        }

        if (c < 7) STORE_CHUNK(nxt);
        __syncthreads();
    }

    // Epilogue: +bias, direct float2 stores (m16n8 C frag layout)
#pragma unroll
    for (int nf = 0; nf < 4; nf++) {
        const int cc = col0 + wn0 + nf * 8 + (lane & 3) * 2;
        const float b0 = bias[cc], b1 = bias[cc + 1];
#pragma unroll
        for (int mf = 0; mf < 4; mf++) {
            const int r = row0 + wm0 + mf * 16 + (lane >> 2);
            float2 o0 = make_float2(acc[mf][nf][0] + b0, acc[mf][nf][1] + b1);
            float2 o1 = make_float2(acc[mf][nf][2] + b0, acc[mf][nf][3] + b1);
            *(float2*)(C + (size_t)r * 256 + cc) = o0;
            *(float2*)(C + (size_t)(r + 8) * 256 + cc) = o1;
        }
    }
}

// ---------------------------------------------------------------------------
// TF32-MMA attention (unchanged from R7): D(64x32) = A(64x80) @ X(80x32).
// ---------------------------------------------------------------------------
__global__ __launch_bounds__(128, 8) void attn_mma(const float* __restrict__ aw,
                                                   const int*   __restrict__ idx,
                                                   const float* __restrict__ wsel)
{
    __shared__ float sXT[32 * 84];   // X^T[ch][tok], 80+4 pad

    const int t    = threadIdx.x;
    const int bid  = blockIdx.x;
    const int blk  = bid & 255;
    const int b    = (bid >> 8) & 7;
    const int h    = bid >> 11;
    const int bh   = blk >> 4;
    const int bw   = blk & 15;
    const int lane = t & 31;
    const int warp = t >> 5;
    const int g    = lane >> 2;
    const int tg   = lane & 3;

    const size_t xbase = (size_t)b * NTOK * 256 + h * 32;

#pragma unroll
    for (int i = 0; i < 4; i++) {
        const int v  = i * 128 + t;
        const int p  = v >> 3;
        const int dq = v & 7;
        const int r  = p >> 3, c = p & 7;
        const int sp = (bh * 8 + r) * 128 + bw * 8 + c;
        const float4 x = *(const float4*)(g_xp + xbase + (size_t)sp * 256 + dq * 4);
        sXT[(dq * 4 + 0) * 84 + p] = tf32r(x.x);
        sXT[(dq * 4 + 1) * 84 + p] = tf32r(x.y);
        sXT[(dq * 4 + 2) * 84 + p] = tf32r(x.z);
        sXT[(dq * 4 + 3) * 84 + p] = tf32r(x.w);
    }
    {
        const int j    = t >> 3;
        const int dq   = t & 7;
        const int base = (b * 256 + blk) * 16 + j;
        const int tok  = idx[base];
        const float w  = wsel[base];
        const float4 x = *(const float4*)(g_xp + xbase + (size_t)tok * 256 + dq * 4);
        sXT[(dq * 4 + 0) * 84 + 64 + j] = tf32r(x.x * w);
        sXT[(dq * 4 + 1) * 84 + 64 + j] = tf32r(x.y * w);
        sXT[(dq * 4 + 2) * 84 + 64 + j] = tf32r(x.z * w);
        sXT[(dq * 4 + 3) * 84 + 64 + j] = tf32r(x.w * w);
    }
    __syncthreads();

    const int m0 = warp << 4;
    const float* Ar0 = aw + (size_t)bid * 5120 + (m0 + g) * 80;
    const float* Ar1 = Ar0 + 8 * 80;

    float acc[4][4];
#pragma unroll
    for (int i = 0; i < 4; i++)
#pragma unroll
        for (int j = 0; j < 4; j++) acc[i][j] = 0.f;

#pragma unroll
    for (int ks = 0; ks < 10; ks++) {
        const int kk = ks * 8;
        uint32_t af[4];
        af[0] = __float_as_uint(tf32r(__ldg(Ar0 + kk + tg)));
        af[1] = __float_as_uint(tf32r(__ldg(Ar1 + kk + tg)));
        af[2] = __float_as_uint(tf32r(__ldg(Ar0 + kk + tg + 4)));
        af[3] = __float_as_uint(tf32r(__ldg(Ar1 + kk + tg + 4)));
#pragma unroll
        for (int nf = 0; nf < 4; nf++) {
            uint32_t bf[2];
            bf[0] = __float_as_uint(sXT[(nf * 8 + g) * 84 + kk + tg]);
            bf[1] = __float_as_uint(sXT[(nf * 8 + g) * 84 + kk + tg + 4]);
            mma_tf32(acc[nf], af, bf);
        }
    }

#pragma unroll
    for (int nf = 0; nf < 4; nf++) {
#pragma unroll
        for (int half = 0; half < 2; half++) {
            const int q  = m0 + g + half * 8;
            const int r  = q >> 3, c = q & 7;
            const int sp = (bh * 8 + r) * 128 + bw * 8 + c;
            const float2 o = make_float2(acc[nf][half * 2 + 0],
                                         acc[nf][half * 2 + 1]);
            *(float2*)(g_y + xbase + (size_t)sp * 256 + nf * 8 + tg * 2) = o;
        }
    }
}

// ===========================================================================
extern "C" void kernel_launch(void* const* d_in, const int* in_sizes, int n_in,
                              void* d_out, int out_size)
{
    const float* x    = (const float*)d_in[0];
    const float* aw   = (const float*)d_in[1];
    const int*   idx  = (const int*)d_in[2];
    const float* wsel = (const float*)d_in[3];
    const float* Win  = (const float*)d_in[4];
    const float* bin  = (const float*)d_in[5];
    const float* Wout = (const float*)d_in[6];
    const float* bout = (const float*)d_in[7];
    float* out = (float*)d_out;

    float *xp_ptr, *y_ptr;
    __half *wt1, *wt2;
    cudaGetSymbolAddress((void**)&xp_ptr, g_xp);
    cudaGetSymbolAddress((void**)&y_ptr, g_y);
    cudaGetSymbolAddress((void**)&wt1, g_wt1);
    cudaGetSymbolAddress((void**)&wt2, g_wt2);

    cudaFuncSetAttribute(gemm_fp16,
                         cudaFuncAttributeMaxDynamicSharedMemorySize, GEMM_SMEM);

    transpose_half<<<64, 256>>>(Win, wt1);
    transpose_half<<<64, 256>>>(Wout, wt2);

    gemm_fp16<<<dim3(2, 1024), 256, GEMM_SMEM>>>(x, wt1, bin, xp_ptr);
    attn_mma<<<16384, 128>>>(aw, idx, wsel);
    gemm_fp16<<<dim3(2, 1024), 256, GEMM_SMEM>>>(y_ptr, wt2, bout, out);
}

// round 10
// speedup vs baseline: 1.3523x; 1.0684x over previous
#include <cuda_runtime.h>
#include <cuda_fp16.h>
#include <cstdint>

#define NTOK 16384

// Scratch (allocation-free rule: __device__ globals)
__device__ float g_xp[33554432];   // x @ W_in
__device__ float g_y[33554432];    // attention output
__device__ __half g_wt1[65536];    // W_in^T  [n][k], fp16
__device__ __half g_wt2[65536];    // W_out^T [n][k], fp16

// ---------------------------------------------------------------------------
__device__ __forceinline__ uint32_t smem_u32(const void* p) {
    uint32_t a;
    asm("{ .reg .u64 t; cvta.to.shared.u64 t, %1; cvt.u32.u64 %0, t; }"
        : "=r"(a) : "l"(p));
    return a;
}
__device__ __forceinline__ void mma_fp16(float* d, const uint32_t* a,
                                         const uint32_t* b) {
    asm volatile(
        "mma.sync.aligned.m16n8k16.row.col.f32.f16.f16.f32 "
        "{%0,%1,%2,%3}, {%4,%5,%6,%7}, {%8,%9}, {%0,%1,%2,%3};"
        : "+f"(d[0]), "+f"(d[1]), "+f"(d[2]), "+f"(d[3])
        : "r"(a[0]), "r"(a[1]), "r"(a[2]), "r"(a[3]), "r"(b[0]), "r"(b[1]));
}
#define LDSM4(R0, R1, R2, R3, addr) \
    asm volatile("ldmatrix.sync.aligned.m8n8.x4.shared.b16 {%0,%1,%2,%3}, [%4];" \
                 : "=r"(R0), "=r"(R1), "=r"(R2), "=r"(R3) : "r"(addr))

// ---------------------------------------------------------------------------
// Transpose + fp16 convert: Wt[n][k] = (half)W[k][n], 256x256
// ---------------------------------------------------------------------------
__global__ void transpose_half(const float* __restrict__ W,
                               __half* __restrict__ Wt)
{
    __shared__ float tile[32][33];
    const int bx = (blockIdx.x & 7) << 5;
    const int by = (blockIdx.x >> 3) << 5;
    const int tx = threadIdx.x & 31;
    const int ty = threadIdx.x >> 5;
#pragma unroll
    for (int i = 0; i < 32; i += 8)
        tile[ty + i][tx] = W[(by + ty + i) * 256 + bx + tx];
    __syncthreads();
#pragma unroll
    for (int i = 0; i < 32; i += 8)
        Wt[(bx + ty + i) * 256 + by + tx] = __float2half_rn(tile[tx][ty + i]);
}

// ---------------------------------------------------------------------------
// Single-pass FP16 warp-MMA GEMM (unchanged from R8)
// ---------------------------------------------------------------------------
#define SROW 80                    // bytes per smem row (32 fp16 + 8 pad)
#define OFF_A 0
#define OFF_B 10240
#define BUFB  20480
#define GEMM_SMEM (2 * BUFB)       // 40960

__global__ __launch_bounds__(256) void gemm_fp16(const float* __restrict__ A,
                                                 const __half* __restrict__ Bt,
                                                 const float* __restrict__ bias,
                                                 float* __restrict__ C)
{
    extern __shared__ char sm[];
    const uint32_t smb = smem_u32(sm);
    const int t    = threadIdx.x;
    const int lane = t & 31;
    const int warp = t >> 5;
    const int wm0  = (warp >> 2) * 64;
    const int wn0  = (warp & 3) * 32;
    const int row0 = blockIdx.y << 7;
    const int col0 = blockIdx.x << 7;

    const int lr = t >> 3;          // 0..31
    const int lk = (t & 7) << 2;    // 0,4,...,28 (element offset)

    float acc[4][4][4];
#pragma unroll
    for (int i = 0; i < 4; i++)
#pragma unroll
        for (int j = 0; j < 4; j++)
#pragma unroll
            for (int k = 0; k < 4; k++) acc[i][j][k] = 0.f;

    float4 pa[4];
    uint2  pb[4];

    const uint32_t aoff = (uint32_t)(wm0 + (lane & 15)) * SROW + ((lane >> 4) << 4);
    const uint32_t boff = (uint32_t)(wn0 + (lane & 15)) * SROW + ((lane >> 4) << 4);

#define LOAD_CHUNK(k0)                                                          \
    do {                                                                        \
        _Pragma("unroll")                                                       \
        for (int i = 0; i < 4; i++) {                                           \
            const int r = i * 32 + lr;                                          \
            pa[i] = *(const float4*)(A  + (size_t)(row0 + r) * 256 + (k0) + lk); \
            pb[i] = *(const uint2*)(Bt + (size_t)(col0 + r) * 256 + (k0) + lk); \
        }                                                                       \
    } while (0)

#define STORE_CHUNK(bufoff)                                                     \
    do {                                                                        \
        char* base = sm + (bufoff);                                             \
        _Pragma("unroll")                                                       \
        for (int i = 0; i < 4; i++) {                                           \
            const int r = i * 32 + lr;                                          \
            const uint32_t off = (uint32_t)r * SROW + ((t & 7) << 3);           \
            uint2 h;                                                            \
            __half2 h0 = __floats2half2_rn(pa[i].x, pa[i].y);                   \
            __half2 h1 = __floats2half2_rn(pa[i].z, pa[i].w);                   \
            h.x = *(uint32_t*)&h0;                                              \
            h.y = *(uint32_t*)&h1;                                              \
            *(uint2*)(base + OFF_A + off) = h;                                  \
            *(uint2*)(base + OFF_B + off) = pb[i];                              \
        }                                                                       \
    } while (0)

    LOAD_CHUNK(0);
    STORE_CHUNK(0);
    __syncthreads();

    for (int c = 0; c < 8; c++) {
        const uint32_t cur = (uint32_t)(c & 1) * BUFB;
        const uint32_t nxt = BUFB - cur;
        if (c < 7) LOAD_CHUNK((c + 1) * 32);

        const uint32_t AB = smb + cur + OFF_A;
        const uint32_t BB = smb + cur + OFF_B;

#pragma unroll
        for (int ks = 0; ks < 2; ks++) {
            const uint32_t kb = ks * 32;   // bytes (16 halves)
            uint32_t ah[4][4], bf[4][2];
#pragma unroll
            for (int mf = 0; mf < 4; mf++)
                LDSM4(ah[mf][0], ah[mf][1], ah[mf][2], ah[mf][3],
                      AB + aoff + mf * (16 * SROW) + kb);
#pragma unroll
            for (int np = 0; np < 2; np++) {
                uint32_t r0, r1, r2, r3;
                LDSM4(r0, r1, r2, r3, BB + boff + np * (16 * SROW) + kb);
                bf[2 * np][0] = r0; bf[2 * np][1] = r2;
                bf[2 * np + 1][0] = r1; bf[2 * np + 1][1] = r3;
            }
#pragma unroll
            for (int mf = 0; mf < 4; mf++)
#pragma unroll
                for (int nf = 0; nf < 4; nf++)
                    mma_fp16(acc[mf][nf], ah[mf], bf[nf]);
        }

        if (c < 7) STORE_CHUNK(nxt);
        __syncthreads();
    }

#pragma unroll
    for (int nf = 0; nf < 4; nf++) {
        const int cc = col0 + wn0 + nf * 8 + (lane & 3) * 2;
        const float b0 = bias[cc], b1 = bias[cc + 1];
#pragma unroll
        for (int mf = 0; mf < 4; mf++) {
            const int r = row0 + wm0 + mf * 16 + (lane >> 2);
            float2 o0 = make_float2(acc[mf][nf][0] + b0, acc[mf][nf][1] + b1);
            float2 o1 = make_float2(acc[mf][nf][2] + b0, acc[mf][nf][3] + b1);
            *(float2*)(C + (size_t)r * 256 + cc) = o0;
            *(float2*)(C + (size_t)(r + 8) * 256 + cc) = o1;
        }
    }
}

// ---------------------------------------------------------------------------
// FP16-MMA attention v3: per (h,b,blk): D(64x32) = A(64x80) @ X(80x32).
//   A staged fp16 [q][k] stride 88 halves, coalesced float4 LDG + cvt;
//   X^T staged fp16 [ch][tok] stride 88. Both consumed via ldmatrix.x4
//   (conflict-free: 11r mod 8 = 3r distinct). 5 k16-steps, 20 MMA/warp.
// ---------------------------------------------------------------------------
#define HROW 88                    // halves per row
#define HROWB (HROW * 2)           // 176 bytes

__global__ __launch_bounds__(128, 8) void attn_mma(const float* __restrict__ aw,
                                                   const int*   __restrict__ idx,
                                                   const float* __restrict__ wsel)
{
    __shared__ __half sA[64 * HROW];    // A[q][k]
    __shared__ __half sXT[32 * HROW];   // X^T[ch][tok]

    const int t    = threadIdx.x;
    const int bid  = blockIdx.x;
    const int blk  = bid & 255;
    const int b    = (bid >> 8) & 7;
    const int h    = bid >> 11;
    const int bh   = blk >> 4;
    const int bw   = blk & 15;
    const int lane = t & 31;
    const int warp = t >> 5;

    const uint32_t sAb  = smem_u32(sA);
    const uint32_t sXTb = smem_u32(sXT);

    // ---- stage A (64x80): 1280 float4 coalesced, 10/thread, cvt to fp16
    const float* Ab = aw + (size_t)bid * 5120;
#pragma unroll
    for (int i = 0; i < 10; i++) {
        const int v = i * 128 + t;
        const int q = v / 20;
        const int m = v % 20;            // float4 index in row
        const float4 a = *(const float4*)(Ab + q * 80 + m * 4);
        __half2 h0 = __floats2half2_rn(a.x, a.y);
        __half2 h1 = __floats2half2_rn(a.z, a.w);
        uint2 hv;
        hv.x = *(uint32_t*)&h0;
        hv.y = *(uint32_t*)&h1;
        *(uint2*)(sA + q * HROW + m * 4) = hv;
    }

    const size_t xbase = (size_t)b * NTOK * 256 + h * 32;

    // ---- stage X^T fp16: local 64 tokens, transposed scalar stores
#pragma unroll
    for (int i = 0; i < 4; i++) {
        const int v  = i * 128 + t;
        const int p  = v >> 3;          // token 0..63
        const int dq = v & 7;           // channel quad
        const int r  = p >> 3, c = p & 7;
        const int sp = (bh * 8 + r) * 128 + bw * 8 + c;
        const float4 x = *(const float4*)(g_xp + xbase + (size_t)sp * 256 + dq * 4);
        sXT[(dq * 4 + 0) * HROW + p] = __float2half_rn(x.x);
        sXT[(dq * 4 + 1) * HROW + p] = __float2half_rn(x.y);
        sXT[(dq * 4 + 2) * HROW + p] = __float2half_rn(x.z);
        sXT[(dq * 4 + 3) * HROW + p] = __float2half_rn(x.w);
    }
    // ---- stage X^T fp16: selected 16 tokens, weighted
    {
        const int j    = t >> 3;
        const int dq   = t & 7;
        const int base = (b * 256 + blk) * 16 + j;
        const int tok  = idx[base];
        const float w  = wsel[base];
        const float4 x = *(const float4*)(g_xp + xbase + (size_t)tok * 256 + dq * 4);
        sXT[(dq * 4 + 0) * HROW + 64 + j] = __float2half_rn(x.x * w);
        sXT[(dq * 4 + 1) * HROW + 64 + j] = __float2half_rn(x.y * w);
        sXT[(dq * 4 + 2) * HROW + 64 + j] = __float2half_rn(x.z * w);
        sXT[(dq * 4 + 3) * HROW + 64 + j] = __float2half_rn(x.w * w);
    }
    __syncthreads();

    // ---- MMA: warp handles rows [m0, m0+16); 5 k16-steps x 4 n8-tiles
    const int m0 = warp << 4;
    const uint32_t aoff = sAb  + (uint32_t)(m0 + (lane & 15)) * HROWB +
                          ((lane >> 4) << 4);
    const uint32_t boff = sXTb + (uint32_t)(lane & 15) * HROWB +
                          ((lane >> 4) << 4);

    float acc[4][4];
#pragma unroll
    for (int i = 0; i < 4; i++)
#pragma unroll
        for (int j = 0; j < 4; j++) acc[i][j] = 0.f;

#pragma unroll
    for (int ks = 0; ks < 5; ks++) {
        const uint32_t kb = ks * 32;    // 16 halves = 32 bytes
        uint32_t ah[4], bf[4][2];
        LDSM4(ah[0], ah[1], ah[2], ah[3], aoff + kb);
#pragma unroll
        for (int np = 0; np < 2; np++) {
            uint32_t r0, r1, r2, r3;
            LDSM4(r0, r1, r2, r3, boff + np * (16 * HROWB) + kb);
            bf[2 * np][0] = r0; bf[2 * np][1] = r2;
            bf[2 * np + 1][0] = r1; bf[2 * np + 1][1] = r3;
        }
#pragma unroll
        for (int nf = 0; nf < 4; nf++)
            mma_fp16(acc[nf], ah, bf[nf]);
    }

    // ---- scatter D to token-major y (c-frag: rows g/g+8, cols 2tg/2tg+1)
    const int g  = lane >> 2;
    const int tg = lane & 3;
#pragma unroll
    for (int nf = 0; nf < 4; nf++) {
#pragma unroll
        for (int half = 0; half < 2; half++) {
            const int q  = m0 + g + half * 8;
            const int r  = q >> 3, c = q & 7;
            const int sp = (bh * 8 + r) * 128 + bw * 8 + c;
            const float2 o = make_float2(acc[nf][half * 2 + 0],
                                         acc[nf][half * 2 + 1]);
            *(float2*)(g_y + xbase + (size_t)sp * 256 + nf * 8 + tg * 2) = o;
        }
    }
}

// ===========================================================================
extern "C" void kernel_launch(void* const* d_in, const int* in_sizes, int n_in,
                              void* d_out, int out_size)
{
    const float* x    = (const float*)d_in[0];
    const float* aw   = (const float*)d_in[1];
    const int*   idx  = (const int*)d_in[2];
    const float* wsel = (const float*)d_in[3];
    const float* Win  = (const float*)d_in[4];
    const float* bin  = (const float*)d_in[5];
    const float* Wout = (const float*)d_in[6];
    const float* bout = (const float*)d_in[7];
    float* out = (float*)d_out;

    float *xp_ptr, *y_ptr;
    __half *wt1, *wt2;
    cudaGetSymbolAddress((void**)&xp_ptr, g_xp);
    cudaGetSymbolAddress((void**)&y_ptr, g_y);
    cudaGetSymbolAddress((void**)&wt1, g_wt1);
    cudaGetSymbolAddress((void**)&wt2, g_wt2);

    cudaFuncSetAttribute(gemm_fp16,
                         cudaFuncAttributeMaxDynamicSharedMemorySize, GEMM_SMEM);

    transpose_half<<<64, 256>>>(Win, wt1);
    transpose_half<<<64, 256>>>(Wout, wt2);

    gemm_fp16<<<dim3(2, 1024), 256, GEMM_SMEM>>>(x, wt1, bin, xp_ptr);
    attn_mma<<<16384, 128>>>(aw, idx, wsel);
    gemm_fp16<<<dim3(2, 1024), 256, GEMM_SMEM>>>(y_ptr, wt2, bout, out);
}

// round 11
// speedup vs baseline: 1.3571x; 1.0036x over previous
#include <cuda_runtime.h>
#include <cuda_fp16.h>
#include <cstdint>

#define NTOK 16384

// Scratch (allocation-free rule: __device__ globals)
__device__ float g_xp[33554432];   // x @ W_in
__device__ float g_y[33554432];    // attention output
__device__ __half g_wt1[65536];    // W_in^T  [n][k], fp16
__device__ __half g_wt2[65536];    // W_out^T [n][k], fp16

// ---------------------------------------------------------------------------
__device__ __forceinline__ uint32_t smem_u32(const void* p) {
    uint32_t a;
    asm("{ .reg .u64 t; cvta.to.shared.u64 t, %1; cvt.u32.u64 %0, t; }"
        : "=r"(a) : "l"(p));
    return a;
}
__device__ __forceinline__ void mma_fp16(float* d, const uint32_t* a,
                                         const uint32_t* b) {
    asm volatile(
        "mma.sync.aligned.m16n8k16.row.col.f32.f16.f16.f32 "
        "{%0,%1,%2,%3}, {%4,%5,%6,%7}, {%8,%9}, {%0,%1,%2,%3};"
        : "+f"(d[0]), "+f"(d[1]), "+f"(d[2]), "+f"(d[3])
        : "r"(a[0]), "r"(a[1]), "r"(a[2]), "r"(a[3]), "r"(b[0]), "r"(b[1]));
}
#define LDSM4(R0, R1, R2, R3, addr) \
    asm volatile("ldmatrix.sync.aligned.m8n8.x4.shared.b16 {%0,%1,%2,%3}, [%4];" \
                 : "=r"(R0), "=r"(R1), "=r"(R2), "=r"(R3) : "r"(addr))

// ---------------------------------------------------------------------------
// Transpose + fp16 convert: Wt[n][k] = (half)W[k][n], 256x256
// ---------------------------------------------------------------------------
__global__ void transpose_half(const float* __restrict__ W,
                               __half* __restrict__ Wt)
{
    __shared__ float tile[32][33];
    const int bx = (blockIdx.x & 7) << 5;
    const int by = (blockIdx.x >> 3) << 5;
    const int tx = threadIdx.x & 31;
    const int ty = threadIdx.x >> 5;
#pragma unroll
    for (int i = 0; i < 32; i += 8)
        tile[ty + i][tx] = W[(by + ty + i) * 256 + bx + tx];
    __syncthreads();
#pragma unroll
    for (int i = 0; i < 32; i += 8)
        Wt[(bx + ty + i) * 256 + by + tx] = __float2half_rn(tile[tx][ty + i]);
}

// ---------------------------------------------------------------------------
// Single-pass FP16 warp-MMA GEMM (unchanged from R8)
// ---------------------------------------------------------------------------
#define SROW 80                    // bytes per smem row (32 fp16 + 8 pad)
#define OFF_A 0
#define OFF_B 10240
#define BUFB  20480
#define GEMM_SMEM (2 * BUFB)       // 40960

__global__ __launch_bounds__(256) void gemm_fp16(const float* __restrict__ A,
                                                 const __half* __restrict__ Bt,
                                                 const float* __restrict__ bias,
                                                 float* __restrict__ C)
{
    extern __shared__ char sm[];
    const uint32_t smb = smem_u32(sm);
    const int t    = threadIdx.x;
    const int lane = t & 31;
    const int warp = t >> 5;
    const int wm0  = (warp >> 2) * 64;
    const int wn0  = (warp & 3) * 32;
    const int row0 = blockIdx.y << 7;
    const int col0 = blockIdx.x << 7;

    const int lr = t >> 3;          // 0..31
    const int lk = (t & 7) << 2;    // 0,4,...,28 (element offset)

    float acc[4][4][4];
#pragma unroll
    for (int i = 0; i < 4; i++)
#pragma unroll
        for (int j = 0; j < 4; j++)
#pragma unroll
            for (int k = 0; k < 4; k++) acc[i][j][k] = 0.f;

    float4 pa[4];
    uint2  pb[4];

    const uint32_t aoff = (uint32_t)(wm0 + (lane & 15)) * SROW + ((lane >> 4) << 4);
    const uint32_t boff = (uint32_t)(wn0 + (lane & 15)) * SROW + ((lane >> 4) << 4);

#define LOAD_CHUNK(k0)                                                          \
    do {                                                                        \
        _Pragma("unroll")                                                       \
        for (int i = 0; i < 4; i++) {                                           \
            const int r = i * 32 + lr;                                          \
            pa[i] = *(const float4*)(A  + (size_t)(row0 + r) * 256 + (k0) + lk); \
            pb[i] = *(const uint2*)(Bt + (size_t)(col0 + r) * 256 + (k0) + lk); \
        }                                                                       \
    } while (0)

#define STORE_CHUNK(bufoff)                                                     \
    do {                                                                        \
        char* base = sm + (bufoff);                                             \
        _Pragma("unroll")                                                       \
        for (int i = 0; i < 4; i++) {                                           \
            const int r = i * 32 + lr;                                          \
            const uint32_t off = (uint32_t)r * SROW + ((t & 7) << 3);           \
            uint2 h;                                                            \
            __half2 h0 = __floats2half2_rn(pa[i].x, pa[i].y);                   \
            __half2 h1 = __floats2half2_rn(pa[i].z, pa[i].w);                   \
            h.x = *(uint32_t*)&h0;                                              \
            h.y = *(uint32_t*)&h1;                                              \
            *(uint2*)(base + OFF_A + off) = h;                                  \
            *(uint2*)(base + OFF_B + off) = pb[i];                              \
        }                                                                       \
    } while (0)

    LOAD_CHUNK(0);
    STORE_CHUNK(0);
    __syncthreads();

    for (int c = 0; c < 8; c++) {
        const uint32_t cur = (uint32_t)(c & 1) * BUFB;
        const uint32_t nxt = BUFB - cur;
        if (c < 7) LOAD_CHUNK((c + 1) * 32);

        const uint32_t AB = smb + cur + OFF_A;
        const uint32_t BB = smb + cur + OFF_B;

#pragma unroll
        for (int ks = 0; ks < 2; ks++) {
            const uint32_t kb = ks * 32;   // bytes (16 halves)
            uint32_t ah[4][4], bf[4][2];
#pragma unroll
            for (int mf = 0; mf < 4; mf++)
                LDSM4(ah[mf][0], ah[mf][1], ah[mf][2], ah[mf][3],
                      AB + aoff + mf * (16 * SROW) + kb);
#pragma unroll
            for (int np = 0; np < 2; np++) {
                uint32_t r0, r1, r2, r3;
                LDSM4(r0, r1, r2, r3, BB + boff + np * (16 * SROW) + kb);
                bf[2 * np][0] = r0; bf[2 * np][1] = r2;
                bf[2 * np + 1][0] = r1; bf[2 * np + 1][1] = r3;
            }
#pragma unroll
            for (int mf = 0; mf < 4; mf++)
#pragma unroll
                for (int nf = 0; nf < 4; nf++)
                    mma_fp16(acc[mf][nf], ah[mf], bf[nf]);
        }

        if (c < 7) STORE_CHUNK(nxt);
        __syncthreads();
    }

#pragma unroll
    for (int nf = 0; nf < 4; nf++) {
        const int cc = col0 + wn0 + nf * 8 + (lane & 3) * 2;
        const float b0 = bias[cc], b1 = bias[cc + 1];
#pragma unroll
        for (int mf = 0; mf < 4; mf++) {
            const int r = row0 + wm0 + mf * 16 + (lane >> 2);
            float2 o0 = make_float2(acc[mf][nf][0] + b0, acc[mf][nf][1] + b1);
            float2 o1 = make_float2(acc[mf][nf][2] + b0, acc[mf][nf][3] + b1);
            *(float2*)(C + (size_t)r * 256 + cc) = o0;
            *(float2*)(C + (size_t)(r + 8) * 256 + cc) = o1;
        }
    }
}

// ---------------------------------------------------------------------------
// FP16-MMA attention v3: per (h,b,blk): D(64x32) = A(64x80) @ X(80x32).
//   A staged fp16 [q][k] stride 88 halves, coalesced float4 LDG + cvt;
//   X^T staged fp16 [ch][tok] stride 88. Both consumed via ldmatrix.x4
//   (conflict-free: 11r mod 8 = 3r distinct). 5 k16-steps, 20 MMA/warp.
// ---------------------------------------------------------------------------
#define HROW 88                    // halves per row
#define HROWB (HROW * 2)           // 176 bytes

__global__ __launch_bounds__(128, 8) void attn_mma(const float* __restrict__ aw,
                                                   const int*   __restrict__ idx,
                                                   const float* __restrict__ wsel)
{
    __shared__ __half sA[64 * HROW];    // A[q][k]
    __shared__ __half sXT[32 * HROW];   // X^T[ch][tok]

    const int t    = threadIdx.x;
    const int bid  = blockIdx.x;
    const int blk  = bid & 255;
    const int b    = (bid >> 8) & 7;
    const int h    = bid >> 11;
    const int bh   = blk >> 4;
    const int bw   = blk & 15;
    const int lane = t & 31;
    const int warp = t >> 5;

    const uint32_t sAb  = smem_u32(sA);
    const uint32_t sXTb = smem_u32(sXT);

    // ---- stage A (64x80): 1280 float4 coalesced, 10/thread, cvt to fp16
    const float* Ab = aw + (size_t)bid * 5120;
#pragma unroll
    for (int i = 0; i < 10; i++) {
        const int v = i * 128 + t;
        const int q = v / 20;
        const int m = v % 20;            // float4 index in row
        const float4 a = *(const float4*)(Ab + q * 80 + m * 4);
        __half2 h0 = __floats2half2_rn(a.x, a.y);
        __half2 h1 = __floats2half2_rn(a.z, a.w);
        uint2 hv;
        hv.x = *(uint32_t*)&h0;
        hv.y = *(uint32_t*)&h1;
        *(uint2*)(sA + q * HROW + m * 4) = hv;
    }

    const size_t xbase = (size_t)b * NTOK * 256 + h * 32;

    // ---- stage X^T fp16: local 64 tokens, transposed scalar stores
#pragma unroll
    for (int i = 0; i < 4; i++) {
        const int v  = i * 128 + t;
        const int p  = v >> 3;          // token 0..63
        const int dq = v & 7;           // channel quad
        const int r  = p >> 3, c = p & 7;
        const int sp = (bh * 8 + r) * 128 + bw * 8 + c;
        const float4 x = *(const float4*)(g_xp + xbase + (size_t)sp * 256 + dq * 4);
        sXT[(dq * 4 + 0) * HROW + p] = __float2half_rn(x.x);
        sXT[(dq * 4 + 1) * HROW + p] = __float2half_rn(x.y);
        sXT[(dq * 4 + 2) * HROW + p] = __float2half_rn(x.z);
        sXT[(dq * 4 + 3) * HROW + p] = __float2half_rn(x.w);
    }
    // ---- stage X^T fp16: selected 16 tokens, weighted
    {
        const int j    = t >> 3;
        const int dq   = t & 7;
        const int base = (b * 256 + blk) * 16 + j;
        const int tok  = idx[base];
        const float w  = wsel[base];
        const float4 x = *(const float4*)(g_xp + xbase + (size_t)tok * 256 + dq * 4);
        sXT[(dq * 4 + 0) * HROW + 64 + j] = __float2half_rn(x.x * w);
        sXT[(dq * 4 + 1) * HROW + 64 + j] = __float2half_rn(x.y * w);
        sXT[(dq * 4 + 2) * HROW + 64 + j] = __float2half_rn(x.z * w);
        sXT[(dq * 4 + 3) * HROW + 64 + j] = __float2half_rn(x.w * w);
    }
    __syncthreads();

    // ---- MMA: warp handles rows [m0, m0+16); 5 k16-steps x 4 n8-tiles
    const int m0 = warp << 4;
    const uint32_t aoff = sAb  + (uint32_t)(m0 + (lane & 15)) * HROWB +
                          ((lane >> 4) << 4);
    const uint32_t boff = sXTb + (uint32_t)(lane & 15) * HROWB +
                          ((lane >> 4) << 4);

    float acc[4][4];
#pragma unroll
    for (int i = 0; i < 4; i++)
#pragma unroll
        for (int j = 0; j < 4; j++) acc[i][j] = 0.f;

#pragma unroll
    for (int ks = 0; ks < 5; ks++) {
        const uint32_t kb = ks * 32;    // 16 halves = 32 bytes
        uint32_t ah[4], bf[4][2];
        LDSM4(ah[0], ah[1], ah[2], ah[3], aoff + kb);
#pragma unroll
        for (int np = 0; np < 2; np++) {
            uint32_t r0, r1, r2, r3;
            LDSM4(r0, r1, r2, r3, boff + np * (16 * HROWB) + kb);
            bf[2 * np][0] = r0; bf[2 * np][1] = r2;
            bf[2 * np + 1][0] = r1; bf[2 * np + 1][1] = r3;
        }
#pragma unroll
        for (int nf = 0; nf < 4; nf++)
            mma_fp16(acc[nf], ah, bf[nf]);
    }

    // ---- scatter D to token-major y (c-frag: rows g/g+8, cols 2tg/2tg+1)
    const int g  = lane >> 2;
    const int tg = lane & 3;
#pragma unroll
    for (int nf = 0; nf < 4; nf++) {
#pragma unroll
        for (int half = 0; half < 2; half++) {
            const int q  = m0 + g + half * 8;
            const int r  = q >> 3, c = q & 7;
            const int sp = (bh * 8 + r) * 128 + bw * 8 + c;
            const float2 o = make_float2(acc[nf][half * 2 + 0],
                                         acc[nf][half * 2 + 1]);
            *(float2*)(g_y + xbase + (size_t)sp * 256 + nf * 8 + tg * 2) = o;
        }
    }
}

// ===========================================================================
extern "C" void kernel_launch(void* const* d_in, const int* in_sizes, int n_in,
                              void* d_out, int out_size)
{
    const float* x    = (const float*)d_in[0];
    const float* aw   = (const float*)d_in[1];
    const int*   idx  = (const int*)d_in[2];
    const float* wsel = (const float*)d_in[3];
    const float* Win  = (const float*)d_in[4];
    const float* bin  = (const float*)d_in[5];
    const float* Wout = (const float*)d_in[6];
    const float* bout = (const float*)d_in[7];
    float* out = (float*)d_out;

    float *xp_ptr, *y_ptr;
    __half *wt1, *wt2;
    cudaGetSymbolAddress((void**)&xp_ptr, g_xp);
    cudaGetSymbolAddress((void**)&y_ptr, g_y);
    cudaGetSymbolAddress((void**)&wt1, g_wt1);
    cudaGetSymbolAddress((void**)&wt2, g_wt2);

    cudaFuncSetAttribute(gemm_fp16,
                         cudaFuncAttributeMaxDynamicSharedMemorySize, GEMM_SMEM);

    transpose_half<<<64, 256>>>(Win, wt1);
    transpose_half<<<64, 256>>>(Wout, wt2);

    gemm_fp16<<<dim3(2, 1024), 256, GEMM_SMEM>>>(x, wt1, bin, xp_ptr);
    attn_mma<<<16384, 128>>>(aw, idx, wsel);
    gemm_fp16<<<dim3(2, 1024), 256, GEMM_SMEM>>>(y_ptr, wt2, bout, out);
}

// round 12
// speedup vs baseline: 1.4656x; 1.0800x over previous
#include <cuda_runtime.h>
#include <cuda_fp16.h>
#include <cstdint>

#define NTOK 16384

// Scratch (allocation-free rule: __device__ globals)
__device__ __half g_xph[33554432];  // x @ W_in, fp16
__device__ __half g_yh[33554432];   // attention output, fp16
__device__ __half g_wt1[65536];     // W_in^T  [n][k], fp16
__device__ __half g_wt2[65536];     // W_out^T [n][k], fp16

// ---------------------------------------------------------------------------
__device__ __forceinline__ uint32_t smem_u32(const void* p) {
    uint32_t a;
    asm("{ .reg .u64 t; cvta.to.shared.u64 t, %1; cvt.u32.u64 %0, t; }"
        : "=r"(a) : "l"(p));
    return a;
}
__device__ __forceinline__ void mma_fp16(float* d, const uint32_t* a,
                                         const uint32_t* b) {
    asm volatile(
        "mma.sync.aligned.m16n8k16.row.col.f32.f16.f16.f32 "
        "{%0,%1,%2,%3}, {%4,%5,%6,%7}, {%8,%9}, {%0,%1,%2,%3};"
        : "+f"(d[0]), "+f"(d[1]), "+f"(d[2]), "+f"(d[3])
        : "r"(a[0]), "r"(a[1]), "r"(a[2]), "r"(a[3]), "r"(b[0]), "r"(b[1]));
}
#define LDSM4(R0, R1, R2, R3, addr) \
    asm volatile("ldmatrix.sync.aligned.m8n8.x4.shared.b16 {%0,%1,%2,%3}, [%4];" \
                 : "=r"(R0), "=r"(R1), "=r"(R2), "=r"(R3) : "r"(addr))
#define CP_ASYNC16(dst, src) \
    asm volatile("cp.async.ca.shared.global [%0], [%1], 16;" \
                 :: "r"(dst), "l"(src))
#define CP_COMMIT() asm volatile("cp.async.commit_group;")
#define CP_WAIT0()  asm volatile("cp.async.wait_group 0;")

// ---------------------------------------------------------------------------
// Transpose + fp16 convert: Wt[n][k] = (half)W[k][n], 256x256
// ---------------------------------------------------------------------------
__global__ void transpose_half(const float* __restrict__ W,
                               __half* __restrict__ Wt)
{
    __shared__ float tile[32][33];
    const int bx = (blockIdx.x & 7) << 5;
    const int by = (blockIdx.x >> 3) << 5;
    const int tx = threadIdx.x & 31;
    const int ty = threadIdx.x >> 5;
#pragma unroll
    for (int i = 0; i < 32; i += 8)
        tile[ty + i][tx] = W[(by + ty + i) * 256 + bx + tx];
    __syncthreads();
#pragma unroll
    for (int i = 0; i < 32; i += 8)
        Wt[(bx + ty + i) * 256 + by + tx] = __float2half_rn(tile[tx][ty + i]);
}

// ---------------------------------------------------------------------------
// GEMM common geometry: CTA 128x128, BK=32, 256 thr, 8 warps (2M x 4N)
// ---------------------------------------------------------------------------
#define SROW 80                    // bytes per smem row (32 fp16 + 8 pad)
#define OFF_A 0
#define OFF_B 10240
#define BUFB  20480
#define GEMM_SMEM (2 * BUFB)       // 40960

// === Variant 1: A fp32 in, C fp16 out (stage 1: xp = x @ W_in) =============
__global__ __launch_bounds__(256) void gemm_f32in_f16out(
    const float* __restrict__ A, const __half* __restrict__ Bt,
    const float* __restrict__ bias, __half* __restrict__ C)
{
    extern __shared__ char sm[];
    const uint32_t smb = smem_u32(sm);
    const int t    = threadIdx.x;
    const int lane = t & 31;
    const int warp = t >> 5;
    const int wm0  = (warp >> 2) * 64;
    const int wn0  = (warp & 3) * 32;
    const int row0 = blockIdx.y << 7;
    const int col0 = blockIdx.x << 7;

    const int lr = t >> 3;
    const int lk = (t & 7) << 2;

    float acc[4][4][4];
#pragma unroll
    for (int i = 0; i < 4; i++)
#pragma unroll
        for (int j = 0; j < 4; j++)
#pragma unroll
            for (int k = 0; k < 4; k++) acc[i][j][k] = 0.f;

    float4 pa[4];
    uint2  pb[4];

    const uint32_t aoff = (uint32_t)(wm0 + (lane & 15)) * SROW + ((lane >> 4) << 4);
    const uint32_t boff = (uint32_t)(wn0 + (lane & 15)) * SROW + ((lane >> 4) << 4);

#define LOAD_CHUNK1(k0)                                                         \
    do {                                                                        \
        _Pragma("unroll")                                                       \
        for (int i = 0; i < 4; i++) {                                           \
            const int r = i * 32 + lr;                                          \
            pa[i] = *(const float4*)(A  + (size_t)(row0 + r) * 256 + (k0) + lk); \
            pb[i] = *(const uint2*)(Bt + (size_t)(col0 + r) * 256 + (k0) + lk); \
        }                                                                       \
    } while (0)

#define STORE_CHUNK1(bufoff)                                                    \
    do {                                                                        \
        char* base = sm + (bufoff);                                             \
        _Pragma("unroll")                                                       \
        for (int i = 0; i < 4; i++) {                                           \
            const int r = i * 32 + lr;                                          \
            const uint32_t off = (uint32_t)r * SROW + ((t & 7) << 3);           \
            uint2 hh;                                                           \
            __half2 h0 = __floats2half2_rn(pa[i].x, pa[i].y);                   \
            __half2 h1 = __floats2half2_rn(pa[i].z, pa[i].w);                   \
            hh.x = *(uint32_t*)&h0;                                             \
            hh.y = *(uint32_t*)&h1;                                             \
            *(uint2*)(base + OFF_A + off) = hh;                                 \
            *(uint2*)(base + OFF_B + off) = pb[i];                              \
        }                                                                       \
    } while (0)

    LOAD_CHUNK1(0);
    STORE_CHUNK1(0);
    __syncthreads();

    for (int c = 0; c < 8; c++) {
        const uint32_t cur = (uint32_t)(c & 1) * BUFB;
        const uint32_t nxt = BUFB - cur;
        if (c < 7) LOAD_CHUNK1((c + 1) * 32);

        const uint32_t AB = smb + cur + OFF_A;
        const uint32_t BB = smb + cur + OFF_B;

#pragma unroll
        for (int ks = 0; ks < 2; ks++) {
            const uint32_t kb = ks * 32;
            uint32_t ah[4][4], bf[4][2];
#pragma unroll
            for (int mf = 0; mf < 4; mf++)
                LDSM4(ah[mf][0], ah[mf][1], ah[mf][2], ah[mf][3],
                      AB + aoff + mf * (16 * SROW) + kb);
#pragma unroll
            for (int np = 0; np < 2; np++) {
                uint32_t r0, r1, r2, r3;
                LDSM4(r0, r1, r2, r3, BB + boff + np * (16 * SROW) + kb);
                bf[2 * np][0] = r0; bf[2 * np][1] = r2;
                bf[2 * np + 1][0] = r1; bf[2 * np + 1][1] = r3;
            }
#pragma unroll
            for (int mf = 0; mf < 4; mf++)
#pragma unroll
                for (int nf = 0; nf < 4; nf++)
                    mma_fp16(acc[mf][nf], ah[mf], bf[nf]);
        }

        if (c < 7) STORE_CHUNK1(nxt);
        __syncthreads();
    }

    // Epilogue: +bias, fp16 stores
#pragma unroll
    for (int nf = 0; nf < 4; nf++) {
        const int cc = col0 + wn0 + nf * 8 + (lane & 3) * 2;
        const float b0 = bias[cc], b1 = bias[cc + 1];
#pragma unroll
        for (int mf = 0; mf < 4; mf++) {
            const int r = row0 + wm0 + mf * 16 + (lane >> 2);
            __half2 o0 = __floats2half2_rn(acc[mf][nf][0] + b0, acc[mf][nf][1] + b1);
            __half2 o1 = __floats2half2_rn(acc[mf][nf][2] + b0, acc[mf][nf][3] + b1);
            *(uint32_t*)(C + (size_t)r * 256 + cc) = *(uint32_t*)&o0;
            *(uint32_t*)(C + (size_t)(r + 8) * 256 + cc) = *(uint32_t*)&o1;
        }
    }
}

// === Variant 2: A fp16 in (cp.async both operands), C fp32 out (stage 3) ===
__global__ __launch_bounds__(256) void gemm_f16in_f32out(
    const __half* __restrict__ A, const __half* __restrict__ Bt,
    const float* __restrict__ bias, float* __restrict__ C)
{
    extern __shared__ char sm[];
    const uint32_t smb = smem_u32(sm);
    const int t    = threadIdx.x;
    const int lane = t & 31;
    const int warp = t >> 5;
    const int wm0  = (warp >> 2) * 64;
    const int wn0  = (warp & 3) * 32;
    const int row0 = blockIdx.y << 7;
    const int col0 = blockIdx.x << 7;

    // cp.async map: v = i*256 + t; r = v>>2 (0..127); seg = v&3 (16B segment)
    const int cr = t >> 2;
    const int cs = t & 3;

    float acc[4][4][4];
#pragma unroll
    for (int i = 0; i < 4; i++)
#pragma unroll
        for (int j = 0; j < 4; j++)
#pragma unroll
            for (int k = 0; k < 4; k++) acc[i][j][k] = 0.f;

    const uint32_t aoff = (uint32_t)(wm0 + (lane & 15)) * SROW + ((lane >> 4) << 4);
    const uint32_t boff = (uint32_t)(wn0 + (lane & 15)) * SROW + ((lane >> 4) << 4);

#define ASYNC_CHUNK2(k0, bufoff)                                                \
    do {                                                                        \
        _Pragma("unroll")                                                       \
        for (int i = 0; i < 2; i++) {                                           \
            const int r = i * 64 + cr;                                          \
            const uint32_t off = (uint32_t)r * SROW + cs * 16;                  \
            CP_ASYNC16(smb + (bufoff) + OFF_A + off,                            \
                       A + (size_t)(row0 + r) * 256 + (k0) + cs * 8);           \
            CP_ASYNC16(smb + (bufoff) + OFF_B + off,                            \
                       Bt + (size_t)(col0 + r) * 256 + (k0) + cs * 8);          \
        }                                                                       \
        CP_COMMIT();                                                            \
    } while (0)

    ASYNC_CHUNK2(0, 0);
    CP_WAIT0();
    __syncthreads();

    for (int c = 0; c < 8; c++) {
        const uint32_t cur = (uint32_t)(c & 1) * BUFB;
        const uint32_t nxt = BUFB - cur;
        if (c < 7) ASYNC_CHUNK2((c + 1) * 32, nxt);

        const uint32_t AB = smb + cur + OFF_A;
        const uint32_t BB = smb + cur + OFF_B;

#pragma unroll
        for (int ks = 0; ks < 2; ks++) {
            const uint32_t kb = ks * 32;
            uint32_t ah[4][4], bf[4][2];
#pragma unroll
            for (int mf = 0; mf < 4; mf++)
                LDSM4(ah[mf][0], ah[mf][1], ah[mf][2], ah[mf][3],
                      AB + aoff + mf * (16 * SROW) + kb);
#pragma unroll
            for (int np = 0; np < 2; np++) {
                uint32_t r0, r1, r2, r3;
                LDSM4(r0, r1, r2, r3, BB + boff + np * (16 * SROW) + kb);
                bf[2 * np][0] = r0; bf[2 * np][1] = r2;
                bf[2 * np + 1][0] = r1; bf[2 * np + 1][1] = r3;
            }
#pragma unroll
            for (int mf = 0; mf < 4; mf++)
#pragma unroll
                for (int nf = 0; nf < 4; nf++)
                    mma_fp16(acc[mf][nf], ah[mf], bf[nf]);
        }

        if (c < 7) CP_WAIT0();
        __syncthreads();
    }

    // Epilogue: +bias, fp32 stores
#pragma unroll
    for (int nf = 0; nf < 4; nf++) {
        const int cc = col0 + wn0 + nf * 8 + (lane & 3) * 2;
        const float b0 = bias[cc], b1 = bias[cc + 1];
#pragma unroll
        for (int mf = 0; mf < 4; mf++) {
            const int r = row0 + wm0 + mf * 16 + (lane >> 2);
            float2 o0 = make_float2(acc[mf][nf][0] + b0, acc[mf][nf][1] + b1);
            float2 o1 = make_float2(acc[mf][nf][2] + b0, acc[mf][nf][3] + b1);
            *(float2*)(C + (size_t)r * 256 + cc) = o0;
            *(float2*)(C + (size_t)(r + 8) * 256 + cc) = o1;
        }
    }
}

// ---------------------------------------------------------------------------
// FP16-MMA attention v4: xp/y in fp16. D(64x32) = A(64x80) @ X(80x32).
// ---------------------------------------------------------------------------
#define HROW 88                    // halves per row
#define HROWB (HROW * 2)           // 176 bytes

__global__ __launch_bounds__(128, 8) void attn_mma(const float* __restrict__ aw,
                                                   const int*   __restrict__ idx,
                                                   const float* __restrict__ wsel)
{
    __shared__ __half sA[64 * HROW];    // A[q][k]
    __shared__ __half sXT[32 * HROW];   // X^T[ch][tok]

    const int t    = threadIdx.x;
    const int bid  = blockIdx.x;
    const int blk  = bid & 255;
    const int b    = (bid >> 8) & 7;
    const int h    = bid >> 11;
    const int bh   = blk >> 4;
    const int bw   = blk & 15;
    const int lane = t & 31;
    const int warp = t >> 5;

    const uint32_t sAb  = smem_u32(sA);
    const uint32_t sXTb = smem_u32(sXT);

    // ---- stage A (64x80): coalesced float4 LDG, 10/thread, cvt to fp16
    const float* Ab = aw + (size_t)bid * 5120;
#pragma unroll
    for (int i = 0; i < 10; i++) {
        const int v = i * 128 + t;
        const int q = v / 20;
        const int m = v % 20;
        const float4 a = *(const float4*)(Ab + q * 80 + m * 4);
        __half2 h0 = __floats2half2_rn(a.x, a.y);
        __half2 h1 = __floats2half2_rn(a.z, a.w);
        uint2 hv;
        hv.x = *(uint32_t*)&h0;
        hv.y = *(uint32_t*)&h1;
        *(uint2*)(sA + q * HROW + m * 4) = hv;
    }

    const size_t xbase = (size_t)b * NTOK * 256 + h * 32;

    // ---- stage X^T: local 64 tokens (fp16 uint2 loads), transposed stores
#pragma unroll
    for (int i = 0; i < 4; i++) {
        const int v  = i * 128 + t;
        const int p  = v >> 3;          // token 0..63
        const int dq = v & 7;           // quad of 4 halves
        const int r  = p >> 3, c = p & 7;
        const int sp = (bh * 8 + r) * 128 + bw * 8 + c;
        const uint2 hv = *(const uint2*)(g_xph + xbase + (size_t)sp * 256 + dq * 4);
        const __half2 h0 = *(const __half2*)&hv.x;
        const __half2 h1 = *(const __half2*)&hv.y;
        sXT[(dq * 4 + 0) * HROW + p] = __low2half(h0);
        sXT[(dq * 4 + 1) * HROW + p] = __high2half(h0);
        sXT[(dq * 4 + 2) * HROW + p] = __low2half(h1);
        sXT[(dq * 4 + 3) * HROW + p] = __high2half(h1);
    }
    // ---- stage X^T: selected 16 tokens, weighted (fp32 mul, fp16 round)
    {
        const int j    = t >> 3;
        const int dq   = t & 7;
        const int base = (b * 256 + blk) * 16 + j;
        const int tok  = idx[base];
        const float w  = wsel[base];
        const uint2 hv = *(const uint2*)(g_xph + xbase + (size_t)tok * 256 + dq * 4);
        const float2 f0 = __half22float2(*(const __half2*)&hv.x);
        const float2 f1 = __half22float2(*(const __half2*)&hv.y);
        sXT[(dq * 4 + 0) * HROW + 64 + j] = __float2half_rn(f0.x * w);
        sXT[(dq * 4 + 1) * HROW + 64 + j] = __float2half_rn(f0.y * w);
        sXT[(dq * 4 + 2) * HROW + 64 + j] = __float2half_rn(f1.x * w);
        sXT[(dq * 4 + 3) * HROW + 64 + j] = __float2half_rn(f1.y * w);
    }
    __syncthreads();

    // ---- MMA: warp handles rows [m0, m0+16); 5 k16-steps x 4 n8-tiles
    const int m0 = warp << 4;
    const uint32_t aoff = sAb  + (uint32_t)(m0 + (lane & 15)) * HROWB +
                          ((lane >> 4) << 4);
    const uint32_t boff = sXTb + (uint32_t)(lane & 15) * HROWB +
                          ((lane >> 4) << 4);

    float acc[4][4];
#pragma unroll
    for (int i = 0; i < 4; i++)
#pragma unroll
        for (int j = 0; j < 4; j++) acc[i][j] = 0.f;

#pragma unroll
    for (int ks = 0; ks < 5; ks++) {
        const uint32_t kb = ks * 32;
        uint32_t ah[4], bf[4][2];
        LDSM4(ah[0], ah[1], ah[2], ah[3], aoff + kb);
#pragma unroll
        for (int np = 0; np < 2; np++) {
            uint32_t r0, r1, r2, r3;
            LDSM4(r0, r1, r2, r3, boff + np * (16 * HROWB) + kb);
            bf[2 * np][0] = r0; bf[2 * np][1] = r2;
            bf[2 * np + 1][0] = r1; bf[2 * np + 1][1] = r3;
        }
#pragma unroll
        for (int nf = 0; nf < 4; nf++)
            mma_fp16(acc[nf], ah, bf[nf]);
    }

    // ---- scatter D (fp16) to token-major y
    const int g  = lane >> 2;
    const int tg = lane & 3;
#pragma unroll
    for (int nf = 0; nf < 4; nf++) {
#pragma unroll
        for (int half = 0; half < 2; half++) {
            const int q  = m0 + g + half * 8;
            const int r  = q >> 3, c = q & 7;
            const int sp = (bh * 8 + r) * 128 + bw * 8 + c;
            __half2 o = __floats2half2_rn(acc[nf][half * 2 + 0],
                                          acc[nf][half * 2 + 1]);
            *(uint32_t*)(g_yh + xbase + (size_t)sp * 256 + nf * 8 + tg * 2) =
                *(uint32_t*)&o;
        }
    }
}

// ===========================================================================
extern "C" void kernel_launch(void* const* d_in, const int* in_sizes, int n_in,
                              void* d_out, int out_size)
{
    const float* x    = (const float*)d_in[0];
    const float* aw   = (const float*)d_in[1];
    const int*   idx  = (const int*)d_in[2];
    const float* wsel = (const float*)d_in[3];
    const float* Win  = (const float*)d_in[4];
    const float* bin  = (const float*)d_in[5];
    const float* Wout = (const float*)d_in[6];
    const float* bout = (const float*)d_in[7];
    float* out = (float*)d_out;

    __half *xph, *yh, *wt1, *wt2;
    cudaGetSymbolAddress((void**)&xph, g_xph);
    cudaGetSymbolAddress((void**)&yh, g_yh);
    cudaGetSymbolAddress((void**)&wt1, g_wt1);
    cudaGetSymbolAddress((void**)&wt2, g_wt2);

    cudaFuncSetAttribute(gemm_f32in_f16out,
                         cudaFuncAttributeMaxDynamicSharedMemorySize, GEMM_SMEM);
    cudaFuncSetAttribute(gemm_f16in_f32out,
                         cudaFuncAttributeMaxDynamicSharedMemorySize, GEMM_SMEM);

    transpose_half<<<64, 256>>>(Win, wt1);
    transpose_half<<<64, 256>>>(Wout, wt2);

    gemm_f32in_f16out<<<dim3(2, 1024), 256, GEMM_SMEM>>>(x, wt1, bin, xph);
    attn_mma<<<16384, 128>>>(aw, idx, wsel);
    gemm_f16in_f32out<<<dim3(2, 1024), 256, GEMM_SMEM>>>(yh, wt2, bout, out);
}